// round 12
// baseline (speedup 1.0000x reference)
#include <cuda_runtime.h>
#include <cuda_fp16.h>
#include <cstdint>

#define NN 100000
#define NE 1600000
#define NB_SETUP 592                 // 148 SMs x 4 co-resident blocks
#define CHUNK 169                    // ceil(NN / NB_SETUP), < 256

#define APAD 136   // As row stride (halves)
#define WPAD 40    // Wts row stride (halves)

// m16n8k16 fp16 MMA, fp32 accumulate (sm_80+ PTX, works on compute_103)
#define MMA16816(c0, c1, c2, c3, a0, a1, a2, a3, b0, b1) \
    asm volatile("mma.sync.aligned.m16n8k16.row.col.f32.f16.f16.f32 " \
        "{%0,%1,%2,%3}, {%4,%5,%6,%7}, {%8,%9}, {%0,%1,%2,%3};" \
        : "+f"(c0), "+f"(c1), "+f"(c2), "+f"(c3) \
        : "r"(a0), "r"(a1), "r"(a2), "r"(a3), "r"(b0), "r"(b1))

// ---------------- device scratch ----------------
__device__ int      g_deg_in[NN];
__device__ int      g_deg_out[NN];
__device__ int      g_cursor[NN];
__device__ float    g_norm_src[NN];
__device__ float    g_norm_dst[NN];
__device__ int      g_row_ptr[NN + 1];
__device__ int      g_csr_src[NE];
__device__ int      g_blk_sum[NB_SETUP];
__device__ int      g_blk_off[NB_SETUP];
__device__ __half2  g_emb_h[(size_t)NN * 64];   // emb * norm_src, fp16
__device__ __half2  g_agg_h[(size_t)NN * 64];   // spmm1 result, fp16
__device__ __half2  g_t_h[(size_t)NN * 32];     // (h1@W2)*norm_src, fp16

// ---------------- software grid barrier (sense-reversing, replay-safe) ----------------
__device__ unsigned g_count = 0;
__device__ volatile unsigned g_gen = 0;

__device__ __forceinline__ void gbar() {
    __syncthreads();
    if (threadIdx.x == 0) {
        __threadfence();
        unsigned gen = g_gen;
        if (atomicAdd(&g_count, 1u) == NB_SETUP - 1) {
            atomicExch(&g_count, 0u);
            __threadfence();
            g_gen = gen + 1;
        } else {
            while (g_gen == gen) { __nanosleep(64); }
        }
        __threadfence();
    }
    __syncthreads();
}

// ---------------- setup 1: zero -> bar -> degree ----------------
__global__ void __launch_bounds__(256, 4)
k_setup1(const int* __restrict__ src, const int* __restrict__ dst,
         int n, int e2, int e) {
    const int gtid = blockIdx.x * 256 + threadIdx.x;
    const int nthr = NB_SETUP * 256;

    for (int i = gtid; i < n; i += nthr) {
        g_deg_in[i] = 0; g_deg_out[i] = 0; g_cursor[i] = 0;
    }
    gbar();
    for (int i = gtid; i < e2; i += nthr) {
        int2 s = ((const int2*)src)[i];
        int2 d = ((const int2*)dst)[i];
        if ((unsigned)s.x < NN) atomicAdd(&g_deg_out[s.x], 1);
        if ((unsigned)s.y < NN) atomicAdd(&g_deg_out[s.y], 1);
        if ((unsigned)d.x < NN) atomicAdd(&g_deg_in[d.x], 1);
        if ((unsigned)d.y < NN) atomicAdd(&g_deg_in[d.y], 1);
    }
    if (gtid == 0 && (e & 1)) {
        int s = src[e - 1], d = dst[e - 1];
        if ((unsigned)s < NN) atomicAdd(&g_deg_out[s], 1);
        if ((unsigned)d < NN) atomicAdd(&g_deg_in[d], 1);
    }
}

// ---------------- setup 2: norms+partials -> bar -> blockscan -> bar -> rowptr -> bar -> fill
__global__ void __launch_bounds__(256, 4)
k_setup2(const int* __restrict__ src, const int* __restrict__ dst,
         int n, int e2, int e) {
    __shared__ int sm[256];
    const int t = threadIdx.x;
    const int b = blockIdx.x;
    const int node = b * CHUNK + t;

    // phase A: norms + per-block degree sums (each thread <=1 node, CHUNK<256)
    int din = 0;
    if (t < CHUNK && node < n) {
        din = g_deg_in[node];
        int dout = g_deg_out[node];
        g_norm_src[node] = rsqrtf((float)(dout < 1 ? 1 : dout));
        g_norm_dst[node] = rsqrtf((float)(din  < 1 ? 1 : din));
    }
    sm[t] = din;
    __syncthreads();
    for (int off = 128; off > 0; off >>= 1) {
        if (t < off) sm[t] += sm[t + off];
        __syncthreads();
    }
    if (t == 0) g_blk_sum[b] = sm[0];
    gbar();

    // phase B: block 0 exclusive-scans the NB_SETUP block sums
    if (b == 0) {
        int v[3]; int s = 0;
#pragma unroll
        for (int j = 0; j < 3; j++) {
            int idx = 3 * t + j;
            v[j] = (idx < NB_SETUP) ? g_blk_sum[idx] : 0;
            s += v[j];
        }
        sm[t] = s;
        __syncthreads();
        for (int off = 1; off < 256; off <<= 1) {
            int add = (t >= off) ? sm[t - off] : 0;
            __syncthreads();
            sm[t] += add;
            __syncthreads();
        }
        int run = (t == 0) ? 0 : sm[t - 1];
#pragma unroll
        for (int j = 0; j < 3; j++) {
            int idx = 3 * t + j;
            if (idx < NB_SETUP) g_blk_off[idx] = run;
            run += v[j];
        }
        if (t == 0) g_row_ptr[n] = e;
    }
    gbar();

    // phase C: per-block exclusive scan -> row_ptr
    sm[t] = din;
    __syncthreads();
    for (int off = 1; off < 256; off <<= 1) {
        int add = (t >= off) ? sm[t - off] : 0;
        __syncthreads();
        sm[t] += add;
        __syncthreads();
    }
    if (t < CHUNK && node < n) g_row_ptr[node] = g_blk_off[b] + sm[t] - din;
    gbar();

    // phase D: CSR fill (2 edges/thread, int2)
    const int gtid = b * 256 + t;
    const int nthr = NB_SETUP * 256;
    for (int i = gtid; i < e2; i += nthr) {
        int2 s2 = ((const int2*)src)[i];
        int2 d2 = ((const int2*)dst)[i];
        if ((unsigned)d2.x < NN && (unsigned)s2.x < NN) {
            int pos = g_row_ptr[d2.x] + atomicAdd(&g_cursor[d2.x], 1);
            g_csr_src[pos] = s2.x;
        }
        if ((unsigned)d2.y < NN && (unsigned)s2.y < NN) {
            int pos = g_row_ptr[d2.y] + atomicAdd(&g_cursor[d2.y], 1);
            g_csr_src[pos] = s2.y;
        }
    }
    if (gtid == 0 && (e & 1)) {
        int s = src[e - 1], d = dst[e - 1];
        if ((unsigned)d < NN && (unsigned)s < NN) {
            int pos = g_row_ptr[d] + atomicAdd(&g_cursor[d], 1);
            g_csr_src[pos] = s;
        }
    }
}

// ---------------- prep: emb * norm_src -> half2, 8 floats/thread ----------------
__global__ void k_prep(const float* __restrict__ emb, int n16) {
    int i = blockIdx.x * blockDim.x + threadIdx.x;
    if (i < n16) {
        int r = i >> 4;
        float4 v0 = ((const float4*)emb)[2 * i];
        float4 v1 = ((const float4*)emb)[2 * i + 1];
        float ns = g_norm_src[r];
        uint4 o;
        *(__half2*)&o.x = __floats2half2_rn(v0.x * ns, v0.y * ns);
        *(__half2*)&o.y = __floats2half2_rn(v0.z * ns, v0.w * ns);
        *(__half2*)&o.z = __floats2half2_rn(v1.x * ns, v1.y * ns);
        *(__half2*)&o.w = __floats2half2_rn(v1.z * ns, v1.w * ns);
        ((uint4*)g_emb_h)[i] = o;
    }
}

// ---------------- SpMM 1 (fp16 gather, fp32 accumulate, fp16 out) ----------------
__global__ void k_spmm1(int n) {
    int w = (blockIdx.x * blockDim.x + threadIdx.x) >> 5;
    int lane = threadIdx.x & 31;
    if (w >= n) return;
    int beg = g_row_ptr[w];
    int end = g_row_ptr[w + 1];
    const uint2* eh = (const uint2*)g_emb_h;   // row = 32 uint2
    float4 acc = make_float4(0.f, 0.f, 0.f, 0.f);
    int ed = beg;
    for (; ed + 3 < end; ed += 4) {
        int s0 = g_csr_src[ed];
        int s1 = g_csr_src[ed + 1];
        int s2 = g_csr_src[ed + 2];
        int s3 = g_csr_src[ed + 3];
        uint2 v0 = eh[(size_t)s0 * 32 + lane];
        uint2 v1 = eh[(size_t)s1 * 32 + lane];
        uint2 v2 = eh[(size_t)s2 * 32 + lane];
        uint2 v3 = eh[(size_t)s3 * 32 + lane];
        float2 a0 = __half22float2(*(__half2*)&v0.x), b0 = __half22float2(*(__half2*)&v0.y);
        float2 a1 = __half22float2(*(__half2*)&v1.x), b1 = __half22float2(*(__half2*)&v1.y);
        float2 a2 = __half22float2(*(__half2*)&v2.x), b2 = __half22float2(*(__half2*)&v2.y);
        float2 a3 = __half22float2(*(__half2*)&v3.x), b3 = __half22float2(*(__half2*)&v3.y);
        acc.x += (a0.x + a1.x) + (a2.x + a3.x);
        acc.y += (a0.y + a1.y) + (a2.y + a3.y);
        acc.z += (b0.x + b1.x) + (b2.x + b3.x);
        acc.w += (b0.y + b1.y) + (b2.y + b3.y);
    }
    for (; ed < end; ed++) {
        int s0 = g_csr_src[ed];
        uint2 v0 = eh[(size_t)s0 * 32 + lane];
        float2 a0 = __half22float2(*(__half2*)&v0.x);
        float2 b0 = __half22float2(*(__half2*)&v0.y);
        acc.x += a0.x; acc.y += a0.y; acc.z += b0.x; acc.w += b0.y;
    }
    float nd = g_norm_dst[w];
    uint2 o;
    *(__half2*)&o.x = __floats2half2_rn(acc.x * nd, acc.y * nd);
    *(__half2*)&o.y = __floats2half2_rn(acc.z * nd, acc.w * nd);
    ((uint2*)g_agg_h)[(size_t)w * 32 + lane] = o;
}

// ---------------- fused GEMM via HMMA (mma.sync m16n8k16) ----------------
__global__ void __launch_bounds__(256)
k_gemm_mma(const float* __restrict__ W1, const float* __restrict__ b1,
           const float* __restrict__ W2, int n) {
    __shared__ __half As[128 * APAD];    // 34.8KB
    __shared__ __half Wts[128 * WPAD];   // 10.2KB, [n][k] transposed chunks
    __shared__ float b1s[128];

    const int tid = threadIdx.x;
    const int lane = tid & 31;
    const int wid = tid >> 5;
    const int row0 = blockIdx.x * 128;
    const int m0 = wid * 16;
    const int r = lane >> 2;          // 0..7
    const int qc = (lane & 3) * 2;    // 0,2,4,6

    // load A tile (fp16, from g_agg_h), zero-pad OOB rows
    for (int i = tid; i < 128 * 32; i += 256) {
        int row = i >> 5, q = i & 31;
        int gr = row0 + row;
        uint2 v = make_uint2(0u, 0u);
        if (gr < n) v = ((const uint2*)g_agg_h)[(size_t)gr * 32 + q];
        *(uint2*)&As[row * APAD + q * 4] = v;
    }
    if (tid < 128) b1s[tid] = b1[tid];

    // ---- phase 1: 16x128 per warp, K=128 ----
    float acc[16][4];
#pragma unroll
    for (int t2 = 0; t2 < 16; t2++)
#pragma unroll
        for (int j = 0; j < 4; j++) acc[t2][j] = 0.f;

    for (int kc = 0; kc < 4; kc++) {
        __syncthreads();
        for (int i = tid; i < 32 * 128; i += 256) {
            int kl = i >> 7, nn = i & 127;
            Wts[nn * WPAD + kl] = __float2half(W1[(kc * 32 + kl) * 128 + nn]);
        }
        __syncthreads();
#pragma unroll
        for (int ks = 0; ks < 2; ks++) {
            int kb = kc * 32 + ks * 16;
            uint32_t a0 = *(uint32_t*)&As[(m0 + r) * APAD + kb + qc];
            uint32_t a1 = *(uint32_t*)&As[(m0 + r + 8) * APAD + kb + qc];
            uint32_t a2 = *(uint32_t*)&As[(m0 + r) * APAD + kb + qc + 8];
            uint32_t a3 = *(uint32_t*)&As[(m0 + r + 8) * APAD + kb + qc + 8];
            int kw = ks * 16;
#pragma unroll
            for (int nt = 0; nt < 16; nt++) {
                uint32_t b0 = *(uint32_t*)&Wts[(nt * 8 + r) * WPAD + kw + qc];
                uint32_t b1f = *(uint32_t*)&Wts[(nt * 8 + r) * WPAD + kw + qc + 8];
                MMA16816(acc[nt][0], acc[nt][1], acc[nt][2], acc[nt][3],
                         a0, a1, a2, a3, b0, b1f);
            }
        }
    }

    // epilogue 1: relu + bias, write h1 fp16 into As (own rows only)
#pragma unroll
    for (int nt = 0; nt < 16; nt++) {
        int c = nt * 8 + qc;
        float x0 = fmaxf(acc[nt][0] + b1s[c],     0.f);
        float x1 = fmaxf(acc[nt][1] + b1s[c + 1], 0.f);
        float x2 = fmaxf(acc[nt][2] + b1s[c],     0.f);
        float x3 = fmaxf(acc[nt][3] + b1s[c + 1], 0.f);
        *(__half2*)&As[(m0 + r) * APAD + c]     = __floats2half2_rn(x0, x1);
        *(__half2*)&As[(m0 + r + 8) * APAD + c] = __floats2half2_rn(x2, x3);
    }

    // ---- phase 2: 16x64 per warp, K=128 ----
    float acc2[8][4];
#pragma unroll
    for (int t2 = 0; t2 < 8; t2++)
#pragma unroll
        for (int j = 0; j < 4; j++) acc2[t2][j] = 0.f;

    for (int kc = 0; kc < 4; kc++) {
        __syncthreads();
        for (int i = tid; i < 32 * 64; i += 256) {
            int kl = i >> 6, nn = i & 63;
            Wts[nn * WPAD + kl] = __float2half(W2[(kc * 32 + kl) * 64 + nn]);
        }
        __syncthreads();
#pragma unroll
        for (int ks = 0; ks < 2; ks++) {
            int kb = kc * 32 + ks * 16;
            uint32_t a0 = *(uint32_t*)&As[(m0 + r) * APAD + kb + qc];
            uint32_t a1 = *(uint32_t*)&As[(m0 + r + 8) * APAD + kb + qc];
            uint32_t a2 = *(uint32_t*)&As[(m0 + r) * APAD + kb + qc + 8];
            uint32_t a3 = *(uint32_t*)&As[(m0 + r + 8) * APAD + kb + qc + 8];
            int kw = ks * 16;
#pragma unroll
            for (int nt = 0; nt < 8; nt++) {
                uint32_t b0 = *(uint32_t*)&Wts[(nt * 8 + r) * WPAD + kw + qc];
                uint32_t b1f = *(uint32_t*)&Wts[(nt * 8 + r) * WPAD + kw + qc + 8];
                MMA16816(acc2[nt][0], acc2[nt][1], acc2[nt][2], acc2[nt][3],
                         a0, a1, a2, a3, b0, b1f);
            }
        }
    }

    // epilogue 2: * norm_src, fp16 store
    {
        int gr0 = row0 + m0 + r;
        int gr1 = gr0 + 8;
        float ns0 = (gr0 < n) ? g_norm_src[gr0] : 0.f;
        float ns1 = (gr1 < n) ? g_norm_src[gr1] : 0.f;
#pragma unroll
        for (int nt = 0; nt < 8; nt++) {
            int c = nt * 8 + qc;   // even
            if (gr0 < n)
                g_t_h[(size_t)gr0 * 32 + (c >> 1)] =
                    __floats2half2_rn(acc2[nt][0] * ns0, acc2[nt][1] * ns0);
            if (gr1 < n)
                g_t_h[(size_t)gr1 * 32 + (c >> 1)] =
                    __floats2half2_rn(acc2[nt][2] * ns1, acc2[nt][3] * ns1);
        }
    }
}

// ---------------- SpMM 2 (fp16 gather, 4-edge unroll) ----------------
__global__ void k_spmm2(const float* __restrict__ b2, float* __restrict__ out, int n) {
    int w = (blockIdx.x * blockDim.x + threadIdx.x) >> 5;
    int lane = threadIdx.x & 31;
    if (w >= n) return;
    int beg = g_row_ptr[w];
    int end = g_row_ptr[w + 1];
    float2 acc = make_float2(0.f, 0.f);
    int ed = beg;
    for (; ed + 3 < end; ed += 4) {
        int s0 = g_csr_src[ed];
        int s1 = g_csr_src[ed + 1];
        int s2 = g_csr_src[ed + 2];
        int s3 = g_csr_src[ed + 3];
        float2 v0 = __half22float2(g_t_h[(size_t)s0 * 32 + lane]);
        float2 v1 = __half22float2(g_t_h[(size_t)s1 * 32 + lane]);
        float2 v2 = __half22float2(g_t_h[(size_t)s2 * 32 + lane]);
        float2 v3 = __half22float2(g_t_h[(size_t)s3 * 32 + lane]);
        acc.x += (v0.x + v1.x) + (v2.x + v3.x);
        acc.y += (v0.y + v1.y) + (v2.y + v3.y);
    }
    for (; ed < end; ed++) {
        int s0 = g_csr_src[ed];
        float2 v0 = __half22float2(g_t_h[(size_t)s0 * 32 + lane]);
        acc.x += v0.x;
        acc.y += v0.y;
    }
    float nd = g_norm_dst[w];
    float2 bb = ((const float2*)b2)[lane];
    float2 o;
    o.x = fmaf(acc.x, nd, bb.x);
    o.y = fmaf(acc.y, nd, bb.y);
    ((float2*)out)[(size_t)w * 32 + lane] = o;
}

// ---------------- launch: 6 kernels, spmm1 is 4th (ncu capture slot) ----------------
extern "C" void kernel_launch(void* const* d_in, const int* in_sizes, int n_in,
                              void* d_out, int out_size) {
    const int* src = (const int*)d_in[1];
    const int* dst = (const int*)d_in[2];
    const float* emb = (const float*)d_in[3];
    const float* W1  = (const float*)d_in[4];
    const float* b1  = (const float*)d_in[5];
    const float* W2  = (const float*)d_in[6];
    const float* b2  = (const float*)d_in[7];
    float* out = (float*)d_out;

    const int n = in_sizes[0];
    const int e = in_sizes[1];
    const int e2 = e >> 1;

    k_setup1<<<NB_SETUP, 256>>>(src, dst, n, e2, e);
    k_setup2<<<NB_SETUP, 256>>>(src, dst, n, e2, e);
    k_prep<<<(n * 16 + 255) / 256, 256>>>(emb, n * 16);

    int warps_grid = (n * 32 + 255) / 256;
    k_spmm1<<<warps_grid, 256>>>(n);                       // 4th launch -> profiled
    k_gemm_mma<<<(n + 127) / 128, 256>>>(W1, b1, W2, n);
    k_spmm2<<<warps_grid, 256>>>(b2, out, n);
}

// round 13
// speedup vs baseline: 1.0892x; 1.0892x over previous
#include <cuda_runtime.h>
#include <cuda_fp16.h>
#include <cstdint>

#define NN 100000
#define NE 1600000
#define SCAN_TILE 1024
#define SCAN_NB ((NN + SCAN_TILE - 1) / SCAN_TILE)   // 98

#define APAD 136   // As row stride (halves)
#define WPAD 40    // Wts row stride (halves)

// m16n8k16 fp16 MMA, fp32 accumulate (sm_80+ PTX, works on compute_103)
#define MMA16816(c0, c1, c2, c3, a0, a1, a2, a3, b0, b1) \
    asm volatile("mma.sync.aligned.m16n8k16.row.col.f32.f16.f16.f32 " \
        "{%0,%1,%2,%3}, {%4,%5,%6,%7}, {%8,%9}, {%0,%1,%2,%3};" \
        : "+f"(c0), "+f"(c1), "+f"(c2), "+f"(c3) \
        : "r"(a0), "r"(a1), "r"(a2), "r"(a3), "r"(b0), "r"(b1))

// ---------------- device scratch ----------------
__device__ int     g_deg_in[NN];
__device__ int     g_deg_out[NN];
__device__ int     g_cursor[NN];
__device__ float   g_norm_src[NN];
__device__ float   g_norm_dst[NN];
__device__ int     g_row_ptr[NN + 1];
__device__ int     g_csr_src[NE];
__device__ int     g_blk_sum[SCAN_NB];
__device__ int     g_blk_off[SCAN_NB];
__device__ __half2 g_emb_h[(size_t)NN * 64];   // emb * norm_src, fp16
__device__ __half2 g_agg_h[(size_t)NN * 64];   // spmm1 result, fp16
__device__ __half2 g_t_h[(size_t)NN * 32];     // (h1@W2)*norm_src, fp16

// ---------------- setup ----------------
__global__ void k_zero(int n) {
    int i = blockIdx.x * blockDim.x + threadIdx.x;
    if (i < n) { g_deg_in[i] = 0; g_deg_out[i] = 0; g_cursor[i] = 0; }
}

__global__ void k_degree(const int* __restrict__ src,
                         const int* __restrict__ dst, int e2, int e) {
    int i = blockIdx.x * blockDim.x + threadIdx.x;
    if (i < e2) {
        int2 s = ((const int2*)src)[i];
        int2 d = ((const int2*)dst)[i];
        if ((unsigned)s.x < NN) atomicAdd(&g_deg_out[s.x], 1);
        if ((unsigned)s.y < NN) atomicAdd(&g_deg_out[s.y], 1);
        if ((unsigned)d.x < NN) atomicAdd(&g_deg_in[d.x], 1);
        if ((unsigned)d.y < NN) atomicAdd(&g_deg_in[d.y], 1);
    } else if (i == e2 && (e & 1)) {
        int s = src[e - 1], d = dst[e - 1];
        if ((unsigned)s < NN) atomicAdd(&g_deg_out[s], 1);
        if ((unsigned)d < NN) atomicAdd(&g_deg_in[d], 1);
    }
}

// emb * norm_src -> half2; 8 floats per thread
__global__ void k_prep(const float* __restrict__ emb, int n16) {
    int i = blockIdx.x * blockDim.x + threadIdx.x;
    if (i < n16) {
        int r = i >> 4;
        float4 v0 = ((const float4*)emb)[2 * i];
        float4 v1 = ((const float4*)emb)[2 * i + 1];
        float ns = g_norm_src[r];
        uint4 o;
        *(__half2*)&o.x = __floats2half2_rn(v0.x * ns, v0.y * ns);
        *(__half2*)&o.y = __floats2half2_rn(v0.z * ns, v0.w * ns);
        *(__half2*)&o.z = __floats2half2_rn(v1.x * ns, v1.y * ns);
        *(__half2*)&o.w = __floats2half2_rn(v1.z * ns, v1.w * ns);
        ((uint4*)g_emb_h)[i] = o;
    }
}

// ---------------- scan phase 1 + norm computation (fused) ----------------
__global__ void __launch_bounds__(256)
k_scan_partial(int n) {
    __shared__ int sm[256];
    int t = threadIdx.x;
    int base = blockIdx.x * SCAN_TILE + t * 4;
    int s = 0;
#pragma unroll
    for (int j = 0; j < 4; j++) {
        int i = base + j;
        if (i < n) {
            int din = g_deg_in[i];
            s += din;
            int dout = g_deg_out[i];
            if (dout < 1) dout = 1;
            if (din  < 1) din  = 1;
            g_norm_src[i] = rsqrtf((float)dout);
            g_norm_dst[i] = rsqrtf((float)din);
        }
    }
    sm[t] = s;
    __syncthreads();
    for (int off = 128; off > 0; off >>= 1) {
        if (t < off) sm[t] += sm[t + off];
        __syncthreads();
    }
    if (t == 0) g_blk_sum[blockIdx.x] = sm[0];
}

__global__ void __launch_bounds__(128)
k_scan_blk(int n, int e) {
    __shared__ int sm[128];
    int t = threadIdx.x;
    int v = (t < SCAN_NB) ? g_blk_sum[t] : 0;
    sm[t] = v;
    __syncthreads();
    for (int off = 1; off < 128; off <<= 1) {
        int add = 0;
        if (t >= off) add = sm[t - off];
        __syncthreads();
        sm[t] += add;
        __syncthreads();
    }
    if (t < SCAN_NB) g_blk_off[t] = sm[t] - v;
    if (t == 0) g_row_ptr[n] = e;
}

__global__ void __launch_bounds__(256)
k_scan_final(int n) {
    __shared__ int sm[256];
    int t = threadIdx.x;
    int base = blockIdx.x * SCAN_TILE + t * 4;
    int d[4];
    int s = 0;
#pragma unroll
    for (int j = 0; j < 4; j++) {
        int i = base + j;
        d[j] = (i < n) ? g_deg_in[i] : 0;
        s += d[j];
    }
    sm[t] = s;
    __syncthreads();
    for (int off = 1; off < 256; off <<= 1) {
        int add = 0;
        if (t >= off) add = sm[t - off];
        __syncthreads();
        sm[t] += add;
        __syncthreads();
    }
    int run = g_blk_off[blockIdx.x] + sm[t] - s;
#pragma unroll
    for (int j = 0; j < 4; j++) {
        int i = base + j;
        if (i < n) g_row_ptr[i] = run;
        run += d[j];
    }
}

__global__ void k_fill(const int* __restrict__ src,
                       const int* __restrict__ dst, int e2, int e) {
    int i = blockIdx.x * blockDim.x + threadIdx.x;
    if (i < e2) {
        int2 s = ((const int2*)src)[i];
        int2 d = ((const int2*)dst)[i];
        if ((unsigned)d.x < NN && (unsigned)s.x < NN) {
            int pos = g_row_ptr[d.x] + atomicAdd(&g_cursor[d.x], 1);
            g_csr_src[pos] = s.x;
        }
        if ((unsigned)d.y < NN && (unsigned)s.y < NN) {
            int pos = g_row_ptr[d.y] + atomicAdd(&g_cursor[d.y], 1);
            g_csr_src[pos] = s.y;
        }
    } else if (i == e2 && (e & 1)) {
        int s = src[e - 1], d = dst[e - 1];
        if ((unsigned)d < NN && (unsigned)s < NN) {
            int pos = g_row_ptr[d] + atomicAdd(&g_cursor[d], 1);
            g_csr_src[pos] = s;
        }
    }
}

// ---------------- SpMM 1: issue-bound -> pairwise HADD2 then fp32 accumulate ----
__global__ void k_spmm1(int n) {
    int w = (blockIdx.x * blockDim.x + threadIdx.x) >> 5;
    int lane = threadIdx.x & 31;
    if (w >= n) return;
    int beg = g_row_ptr[w];
    int end = g_row_ptr[w + 1];
    const uint2* eh = (const uint2*)g_emb_h;   // row = 32 uint2
    float4 acc = make_float4(0.f, 0.f, 0.f, 0.f);
    int ed = beg;
    for (; ed + 3 < end; ed += 4) {
        int s0 = g_csr_src[ed];
        int s1 = g_csr_src[ed + 1];
        int s2 = g_csr_src[ed + 2];
        int s3 = g_csr_src[ed + 3];
        uint2 v0 = eh[(size_t)s0 * 32 + lane];
        uint2 v1 = eh[(size_t)s1 * 32 + lane];
        uint2 v2 = eh[(size_t)s2 * 32 + lane];
        uint2 v3 = eh[(size_t)s3 * 32 + lane];
        // pairwise fp16 adds (1 rounding per pair), then fp32 accumulate
        __half2 px01 = __hadd2(*(__half2*)&v0.x, *(__half2*)&v1.x);
        __half2 py01 = __hadd2(*(__half2*)&v0.y, *(__half2*)&v1.y);
        __half2 px23 = __hadd2(*(__half2*)&v2.x, *(__half2*)&v3.x);
        __half2 py23 = __hadd2(*(__half2*)&v2.y, *(__half2*)&v3.y);
        float2 a01 = __half22float2(px01), b01 = __half22float2(py01);
        float2 a23 = __half22float2(px23), b23 = __half22float2(py23);
        acc.x += a01.x + a23.x;
        acc.y += a01.y + a23.y;
        acc.z += b01.x + b23.x;
        acc.w += b01.y + b23.y;
    }
    for (; ed < end; ed++) {
        int s0 = g_csr_src[ed];
        uint2 v0 = eh[(size_t)s0 * 32 + lane];
        float2 a0 = __half22float2(*(__half2*)&v0.x);
        float2 b0 = __half22float2(*(__half2*)&v0.y);
        acc.x += a0.x; acc.y += a0.y; acc.z += b0.x; acc.w += b0.y;
    }
    float nd = g_norm_dst[w];
    uint2 o;
    *(__half2*)&o.x = __floats2half2_rn(acc.x * nd, acc.y * nd);
    *(__half2*)&o.y = __floats2half2_rn(acc.z * nd, acc.w * nd);
    ((uint2*)g_agg_h)[(size_t)w * 32 + lane] = o;
}

// ---------------- fused GEMM via HMMA (mma.sync m16n8k16) ----------------
__global__ void __launch_bounds__(256)
k_gemm_mma(const float* __restrict__ W1, const float* __restrict__ b1,
           const float* __restrict__ W2, int n) {
    __shared__ __half As[128 * APAD];    // 34.8KB
    __shared__ __half Wts[128 * WPAD];   // 10.2KB, [n][k] transposed chunks
    __shared__ float b1s[128];

    const int tid = threadIdx.x;
    const int lane = tid & 31;
    const int wid = tid >> 5;
    const int row0 = blockIdx.x * 128;
    const int m0 = wid * 16;
    const int r = lane >> 2;          // 0..7
    const int qc = (lane & 3) * 2;    // 0,2,4,6

    // load A tile (fp16, from g_agg_h), zero-pad OOB rows
    for (int i = tid; i < 128 * 32; i += 256) {
        int row = i >> 5, q = i & 31;
        int gr = row0 + row;
        uint2 v = make_uint2(0u, 0u);
        if (gr < n) v = ((const uint2*)g_agg_h)[(size_t)gr * 32 + q];
        *(uint2*)&As[row * APAD + q * 4] = v;
    }
    if (tid < 128) b1s[tid] = b1[tid];

    // ---- phase 1: 16x128 per warp, K=128 ----
    float acc[16][4];
#pragma unroll
    for (int t2 = 0; t2 < 16; t2++)
#pragma unroll
        for (int j = 0; j < 4; j++) acc[t2][j] = 0.f;

    for (int kc = 0; kc < 4; kc++) {
        __syncthreads();
        for (int i = tid; i < 32 * 128; i += 256) {
            int kl = i >> 7, nn = i & 127;
            Wts[nn * WPAD + kl] = __float2half(W1[(kc * 32 + kl) * 128 + nn]);
        }
        __syncthreads();
#pragma unroll
        for (int ks = 0; ks < 2; ks++) {
            int kb = kc * 32 + ks * 16;
            uint32_t a0 = *(uint32_t*)&As[(m0 + r) * APAD + kb + qc];
            uint32_t a1 = *(uint32_t*)&As[(m0 + r + 8) * APAD + kb + qc];
            uint32_t a2 = *(uint32_t*)&As[(m0 + r) * APAD + kb + qc + 8];
            uint32_t a3 = *(uint32_t*)&As[(m0 + r + 8) * APAD + kb + qc + 8];
            int kw = ks * 16;
#pragma unroll
            for (int nt = 0; nt < 16; nt++) {
                uint32_t b0 = *(uint32_t*)&Wts[(nt * 8 + r) * WPAD + kw + qc];
                uint32_t b1f = *(uint32_t*)&Wts[(nt * 8 + r) * WPAD + kw + qc + 8];
                MMA16816(acc[nt][0], acc[nt][1], acc[nt][2], acc[nt][3],
                         a0, a1, a2, a3, b0, b1f);
            }
        }
    }

    // epilogue 1: relu + bias, write h1 fp16 into As (own rows only)
#pragma unroll
    for (int nt = 0; nt < 16; nt++) {
        int c = nt * 8 + qc;
        float x0 = fmaxf(acc[nt][0] + b1s[c],     0.f);
        float x1 = fmaxf(acc[nt][1] + b1s[c + 1], 0.f);
        float x2 = fmaxf(acc[nt][2] + b1s[c],     0.f);
        float x3 = fmaxf(acc[nt][3] + b1s[c + 1], 0.f);
        *(__half2*)&As[(m0 + r) * APAD + c]     = __floats2half2_rn(x0, x1);
        *(__half2*)&As[(m0 + r + 8) * APAD + c] = __floats2half2_rn(x2, x3);
    }

    // ---- phase 2: 16x64 per warp, K=128 ----
    float acc2[8][4];
#pragma unroll
    for (int t2 = 0; t2 < 8; t2++)
#pragma unroll
        for (int j = 0; j < 4; j++) acc2[t2][j] = 0.f;

    for (int kc = 0; kc < 4; kc++) {
        __syncthreads();
        for (int i = tid; i < 32 * 64; i += 256) {
            int kl = i >> 6, nn = i & 63;
            Wts[nn * WPAD + kl] = __float2half(W2[(kc * 32 + kl) * 64 + nn]);
        }
        __syncthreads();
#pragma unroll
        for (int ks = 0; ks < 2; ks++) {
            int kb = kc * 32 + ks * 16;
            uint32_t a0 = *(uint32_t*)&As[(m0 + r) * APAD + kb + qc];
            uint32_t a1 = *(uint32_t*)&As[(m0 + r + 8) * APAD + kb + qc];
            uint32_t a2 = *(uint32_t*)&As[(m0 + r) * APAD + kb + qc + 8];
            uint32_t a3 = *(uint32_t*)&As[(m0 + r + 8) * APAD + kb + qc + 8];
            int kw = ks * 16;
#pragma unroll
            for (int nt = 0; nt < 8; nt++) {
                uint32_t b0 = *(uint32_t*)&Wts[(nt * 8 + r) * WPAD + kw + qc];
                uint32_t b1f = *(uint32_t*)&Wts[(nt * 8 + r) * WPAD + kw + qc + 8];
                MMA16816(acc2[nt][0], acc2[nt][1], acc2[nt][2], acc2[nt][3],
                         a0, a1, a2, a3, b0, b1f);
            }
        }
    }

    // epilogue 2: * norm_src, fp16 store
    {
        int gr0 = row0 + m0 + r;
        int gr1 = gr0 + 8;
        float ns0 = (gr0 < n) ? g_norm_src[gr0] : 0.f;
        float ns1 = (gr1 < n) ? g_norm_src[gr1] : 0.f;
#pragma unroll
        for (int nt = 0; nt < 8; nt++) {
            int c = nt * 8 + qc;   // even
            if (gr0 < n)
                g_t_h[(size_t)gr0 * 32 + (c >> 1)] =
                    __floats2half2_rn(acc2[nt][0] * ns0, acc2[nt][1] * ns0);
            if (gr1 < n)
                g_t_h[(size_t)gr1 * 32 + (c >> 1)] =
                    __floats2half2_rn(acc2[nt][2] * ns1, acc2[nt][3] * ns1);
        }
    }
}

// ---------------- SpMM 2 (pairwise HADD2, fp32 accumulate) ----------------
__global__ void k_spmm2(const float* __restrict__ b2, float* __restrict__ out, int n) {
    int w = (blockIdx.x * blockDim.x + threadIdx.x) >> 5;
    int lane = threadIdx.x & 31;
    if (w >= n) return;
    int beg = g_row_ptr[w];
    int end = g_row_ptr[w + 1];
    float2 acc = make_float2(0.f, 0.f);
    int ed = beg;
    for (; ed + 3 < end; ed += 4) {
        int s0 = g_csr_src[ed];
        int s1 = g_csr_src[ed + 1];
        int s2 = g_csr_src[ed + 2];
        int s3 = g_csr_src[ed + 3];
        __half2 t0 = g_t_h[(size_t)s0 * 32 + lane];
        __half2 t1 = g_t_h[(size_t)s1 * 32 + lane];
        __half2 t2 = g_t_h[(size_t)s2 * 32 + lane];
        __half2 t3 = g_t_h[(size_t)s3 * 32 + lane];
        float2 p01 = __half22float2(__hadd2(t0, t1));
        float2 p23 = __half22float2(__hadd2(t2, t3));
        acc.x += p01.x + p23.x;
        acc.y += p01.y + p23.y;
    }
    for (; ed < end; ed++) {
        int s0 = g_csr_src[ed];
        float2 v0 = __half22float2(g_t_h[(size_t)s0 * 32 + lane]);
        acc.x += v0.x;
        acc.y += v0.y;
    }
    float nd = g_norm_dst[w];
    float2 bb = ((const float2*)b2)[lane];
    float2 o;
    o.x = fmaf(acc.x, nd, bb.x);
    o.y = fmaf(acc.y, nd, bb.y);
    ((float2*)out)[(size_t)w * 32 + lane] = o;
}

// ---------------- launch ----------------
extern "C" void kernel_launch(void* const* d_in, const int* in_sizes, int n_in,
                              void* d_out, int out_size) {
    const int* src = (const int*)d_in[1];
    const int* dst = (const int*)d_in[2];
    const float* emb = (const float*)d_in[3];
    const float* W1  = (const float*)d_in[4];
    const float* b1  = (const float*)d_in[5];
    const float* W2  = (const float*)d_in[6];
    const float* b2  = (const float*)d_in[7];
    float* out = (float*)d_out;

    const int n = in_sizes[0];
    const int e = in_sizes[1];
    const int e2 = e >> 1;

    k_zero<<<(n + 255) / 256, 256>>>(n);
    k_degree<<<(e2 + 256) / 256, 256>>>(src, dst, e2, e);
    k_scan_partial<<<SCAN_NB, 256>>>(n);     // also computes norms
    k_prep<<<(n * 16 + 255) / 256, 256>>>(emb, n * 16);
    k_scan_blk<<<1, 128>>>(n, e);
    k_scan_final<<<SCAN_NB, 256>>>(n);
    k_fill<<<(e2 + 256) / 256, 256>>>(src, dst, e2, e);

    int warps_grid = (n * 32 + 255) / 256;
    k_spmm1<<<warps_grid, 256>>>(n);
    k_gemm_mma<<<(n + 127) / 128, 256>>>(W1, b1, W2, n);
    k_spmm2<<<warps_grid, 256>>>(b2, out, n);
}